// round 1
// baseline (speedup 1.0000x reference)
#include <cuda_runtime.h>

// Problem constants
#define BATCH   1024
#define D_SZ    384
#define K_WIDE  (D_SZ * D_SZ)     // 147456
#define N_OUT   (2 * D_SZ)        // 768
#define OUT_STR (4 * D_SZ)        // 1536

// ---------------------------------------------------------------------------
// f32 -> tf32 with round-to-nearest (unbiased; truncation would bias the
// K=147456 accumulation by ~2^-11 systematically)
// ---------------------------------------------------------------------------
__device__ __forceinline__ float f2tf32(float x) {
    unsigned r;
    asm("cvt.rna.tf32.f32 %0, %1;" : "=r"(r) : "f"(x));
    return __uint_as_float(r);
}

__device__ __forceinline__ void mma_tf32(float c[4], const unsigned a[4], const unsigned b[2]) {
    asm volatile(
        "mma.sync.aligned.m16n8k8.row.col.f32.tf32.tf32.f32 "
        "{%0,%1,%2,%3}, {%4,%5,%6,%7}, {%8,%9}, {%0,%1,%2,%3};\n"
        : "+f"(c[0]), "+f"(c[1]), "+f"(c[2]), "+f"(c[3])
        : "r"(a[0]), "r"(a[1]), "r"(a[2]), "r"(a[3]),
          "r"(b[0]), "r"(b[1]));
}

// ---------------------------------------------------------------------------
// Deep path:  g = [hs|ht] @ W_L^T + b_L   -> out[:, 0:768]
// Also initializes out[:, 768:1536] = b_L2 (wide kernel atomically adds onto it)
// ---------------------------------------------------------------------------
#define DBM 64
#define DBN 64
#define DBK 16

__global__ __launch_bounds__(256)
void deep_kernel(const float* __restrict__ hs, const float* __restrict__ ht,
                 const float* __restrict__ WL, const float* __restrict__ bL,
                 const float* __restrict__ bL2, float* __restrict__ out)
{
    __shared__ float Xs[DBK][DBM + 8];
    __shared__ float Ws[DBK][DBN + 8];

    const int tid = threadIdx.x;
    const int tx  = tid & 15;       // n direction (16)
    const int ty  = tid >> 4;       // m direction (16)
    const int m0  = blockIdx.x * DBM;
    const int n0  = blockIdx.y * DBN;

    float acc[4][4];
#pragma unroll
    for (int i = 0; i < 4; ++i)
#pragma unroll
        for (int j = 0; j < 4; ++j) acc[i][j] = 0.f;

    for (int k0 = 0; k0 < 2 * D_SZ; k0 += DBK) {
        __syncthreads();
#pragma unroll
        for (int q = 0; q < 4; ++q) {
            int e  = tid + 256 * q;
            int kk = e & 15;
            int mm = e >> 4;        // 0..63
            int gk = k0 + kk;
            float xv = (gk < D_SZ) ? hs[(m0 + mm) * D_SZ + gk]
                                   : ht[(m0 + mm) * D_SZ + (gk - D_SZ)];
            Xs[kk][mm] = xv;
            Ws[kk][mm] = WL[(size_t)(n0 + mm) * (2 * D_SZ) + gk];
        }
        __syncthreads();
#pragma unroll
        for (int kk = 0; kk < DBK; ++kk) {
            float4 av = *(const float4*)&Xs[kk][ty * 4];
            float4 bv = *(const float4*)&Ws[kk][tx * 4];
            float a[4] = {av.x, av.y, av.z, av.w};
            float b[4] = {bv.x, bv.y, bv.z, bv.w};
#pragma unroll
            for (int i = 0; i < 4; ++i)
#pragma unroll
                for (int j = 0; j < 4; ++j) acc[i][j] += a[i] * b[j];
        }
    }

#pragma unroll
    for (int i = 0; i < 4; ++i) {
        int row = m0 + ty * 4 + i;
#pragma unroll
        for (int j = 0; j < 4; ++j) {
            int col = n0 + tx * 4 + j;
            out[(size_t)row * OUT_STR + col]         = acc[i][j] + bL[col];
            out[(size_t)row * OUT_STR + N_OUT + col] = bL2[col];   // bias init for wide path
        }
    }
}

// ---------------------------------------------------------------------------
// Wide path: u[b,o] = sum_k A[b,k] * W2[o,k],  A[b, i*D+j] = hs[b,i]*ht[b,j]
// GEMM M=1024 N=768 K=147456, tf32 mma.sync, A built on the fly.
// Grid: (M tiles fastest -> L2 reuse of W across M-CTAs, N tiles, K-split=4)
// ---------------------------------------------------------------------------
#define BM 128
#define BN 64
#define BK 16
#define LDT (BK + 4)               // 20: fragment LDS maps lane->bank identity
#define KSPLIT 4
#define KSLICE (K_WIDE / KSPLIT)   // 36864 = 96 i-values
#define NCHUNK (KSLICE / BK)       // 2304
#define CH_PER_I (D_SZ / BK)       // 24

struct StageRegs {
    float4 w;          // W2 tile fragment (1 float4/thread)
    float4 a0, a1;     // ht tile fragments
    float  h0, h1;     // hs scalars
};

__device__ __forceinline__ void load_stage(
    StageRegs& s, const float* __restrict__ hs, const float* __restrict__ ht,
    const float* __restrict__ W2, int m0, int n0, size_t gk, int i, int j0, int tid)
{
    const int row = tid >> 2;            // 0..63
    const int kv  = (tid & 3) * 4;       // 0,4,8,12
    s.w  = *(const float4*)(W2 + (size_t)(n0 + row) * K_WIDE + gk + kv);
    s.a0 = *(const float4*)(ht + (size_t)(m0 + row)      * D_SZ + j0 + kv);
    s.a1 = *(const float4*)(ht + (size_t)(m0 + row + 64) * D_SZ + j0 + kv);
    s.h0 = hs[(size_t)(m0 + row)      * D_SZ + i];
    s.h1 = hs[(size_t)(m0 + row + 64) * D_SZ + i];
}

__device__ __forceinline__ void store_stage(
    const StageRegs& s, float (*As)[LDT], float (*Ws)[LDT], int tid)
{
    const int row = tid >> 2;
    const int kv  = (tid & 3) * 4;
    float4 wv;
    wv.x = f2tf32(s.w.x); wv.y = f2tf32(s.w.y);
    wv.z = f2tf32(s.w.z); wv.w = f2tf32(s.w.w);
    *(float4*)&Ws[row][kv] = wv;

    float4 v0;
    v0.x = f2tf32(s.h0 * s.a0.x); v0.y = f2tf32(s.h0 * s.a0.y);
    v0.z = f2tf32(s.h0 * s.a0.z); v0.w = f2tf32(s.h0 * s.a0.w);
    *(float4*)&As[row][kv] = v0;

    float4 v1;
    v1.x = f2tf32(s.h1 * s.a1.x); v1.y = f2tf32(s.h1 * s.a1.y);
    v1.z = f2tf32(s.h1 * s.a1.z); v1.w = f2tf32(s.h1 * s.a1.w);
    *(float4*)&As[row + 64][kv] = v1;
}

__device__ __forceinline__ void compute_chunk(
    float acc[2][4][4], const float (*As)[LDT], const float (*Ws)[LDT],
    int wm, int wn, int lane)
{
    const int r = lane >> 2;
    const int c = lane & 3;
#pragma unroll
    for (int ks = 0; ks < BK; ks += 8) {
        unsigned a[2][4], b[4][2];
#pragma unroll
        for (int mi = 0; mi < 2; ++mi) {
            int mb = wm + 16 * mi;
            a[mi][0] = __float_as_uint(As[mb + r    ][ks + c    ]);
            a[mi][1] = __float_as_uint(As[mb + r + 8][ks + c    ]);
            a[mi][2] = __float_as_uint(As[mb + r    ][ks + c + 4]);
            a[mi][3] = __float_as_uint(As[mb + r + 8][ks + c + 4]);
        }
#pragma unroll
        for (int ni = 0; ni < 4; ++ni) {
            int nb = wn + 8 * ni;
            b[ni][0] = __float_as_uint(Ws[nb + r][ks + c    ]);
            b[ni][1] = __float_as_uint(Ws[nb + r][ks + c + 4]);
        }
#pragma unroll
        for (int mi = 0; mi < 2; ++mi)
#pragma unroll
            for (int ni = 0; ni < 4; ++ni)
                mma_tf32(acc[mi][ni], a[mi], b[ni]);
    }
}

__global__ __launch_bounds__(256, 2)
void wide_kernel(const float* __restrict__ hs, const float* __restrict__ ht,
                 const float* __restrict__ W2, float* __restrict__ out)
{
    __shared__ float As[2][BM][LDT];   // tf32-converted A tile
    __shared__ float Ws[2][BN][LDT];   // tf32-converted W tile

    const int tid  = threadIdx.x;
    const int lane = tid & 31;
    const int warp = tid >> 5;
    const int wm = (warp & 3) * 32;    // warp m offset in tile
    const int wn = (warp >> 2) * 32;   // warp n offset in tile

    const int m0 = blockIdx.x * BM;
    const int n0 = blockIdx.y * BN;
    const int z  = blockIdx.z;
    const size_t kbase = (size_t)z * KSLICE;
    const int i0 = z * (KSLICE / D_SZ);   // z*96

    float acc[2][4][4];
#pragma unroll
    for (int mi = 0; mi < 2; ++mi)
#pragma unroll
        for (int ni = 0; ni < 4; ++ni)
#pragma unroll
            for (int q = 0; q < 4; ++q) acc[mi][ni][q] = 0.f;

    // prologue: stage chunk 0
    StageRegs s;
    load_stage(s, hs, ht, W2, m0, n0, kbase, i0, 0, tid);
    store_stage(s, As[0], Ws[0], tid);
    __syncthreads();

#pragma unroll 1
    for (int ch = 0; ch < NCHUNK; ++ch) {
        const int buf = ch & 1;
        const bool has_next = (ch + 1 < NCHUNK);
        if (has_next) {
            int cn = ch + 1;
            int in = i0 + cn / CH_PER_I;
            int jn = (cn % CH_PER_I) * BK;
            load_stage(s, hs, ht, W2, m0, n0, kbase + (size_t)cn * BK, in, jn, tid);
        }
        compute_chunk(acc, As[buf], Ws[buf], wm, wn, lane);
        if (has_next) {
            store_stage(s, As[buf ^ 1], Ws[buf ^ 1], tid);
            __syncthreads();
        }
    }

    // epilogue: atomic accumulate onto bias-initialized out[:, 768:1536]
    const int r = lane >> 2;
    const int c = lane & 3;
#pragma unroll
    for (int mi = 0; mi < 2; ++mi) {
#pragma unroll
        for (int ni = 0; ni < 4; ++ni) {
            int row  = m0 + wm + 16 * mi + r;
            int col0 = N_OUT + n0 + wn + 8 * ni + 2 * c;
            float* p0 = &out[(size_t)row * OUT_STR + col0];
            atomicAdd(p0,     acc[mi][ni][0]);
            atomicAdd(p0 + 1, acc[mi][ni][1]);
            float* p1 = &out[(size_t)(row + 8) * OUT_STR + col0];
            atomicAdd(p1,     acc[mi][ni][2]);
            atomicAdd(p1 + 1, acc[mi][ni][3]);
        }
    }
}

// ---------------------------------------------------------------------------
extern "C" void kernel_launch(void* const* d_in, const int* in_sizes, int n_in,
                              void* d_out, int out_size)
{
    const float* hs  = (const float*)d_in[0];
    const float* ht  = (const float*)d_in[1];
    const float* WL  = (const float*)d_in[2];
    const float* bL  = (const float*)d_in[3];
    const float* W2  = (const float*)d_in[4];
    const float* bL2 = (const float*)d_in[5];
    float* out = (float*)d_out;

    // deep path + bias init of wide region (must precede wide kernel's atomics;
    // same-stream ordering guarantees it, graph capture preserves the edge)
    deep_kernel<<<dim3(BATCH / DBM, N_OUT / DBN), 256>>>(hs, ht, WL, bL, bL2, out);

    // wide path: M fastest in grid -> co-scheduled M-CTAs share W slices in L2
    wide_kernel<<<dim3(BATCH / BM, N_OUT / BN, KSPLIT), 256>>>(hs, ht, W2, out);
}

// round 5
// speedup vs baseline: 2.4989x; 2.4989x over previous
#include <cuda_runtime.h>
#include <cstdint>

// ---------------------------------------------------------------------------
// Problem constants
// ---------------------------------------------------------------------------
#define BATCH   1024
#define D_SZ    384
#define K_WIDE  (D_SZ * D_SZ)      // 147456
#define N_OUT   (2 * D_SZ)         // 768
#define OUT_STR (4 * D_SZ)         // 1536

// ---------------------------------------------------------------------------
// Wide-path GEMM config: M=1024 N=768 K=147456, A = hs x ht generated on-fly
// ---------------------------------------------------------------------------
#define BM      128
#define BN      128
#define BKC     32                  // k-floats per chunk
#define KSPLIT  3
#define KSLICE  (K_WIDE / KSPLIT)   // 49152 = 128 i-values
#define IPG     8                   // i-values per hs staging group
#define NCH     (KSLICE / BKC)      // 1536 chunks per CTA
#define LDT     36                  // row stride words: BKC=32 + 4 pad (R3/R4 bug was 20!)
#define NTH     512
#define NBUF    3

#define B_WORDS   (BN * LDT)            // per B buffer
#define HTS_WORDS (BM * LDT)
#define HSS_WORDS (IPG * BM)
#define SMEM_WORDS (NBUF * B_WORDS + HTS_WORDS + HSS_WORDS)
#define SMEM_BYTES (SMEM_WORDS * 4)     // 77824 B -> dynamic smem

__device__ __forceinline__ void cp_async16(uint32_t dst, const void* src) {
    asm volatile("cp.async.cg.shared.global [%0], [%1], 16;" :: "r"(dst), "l"(src) : "memory");
}
__device__ __forceinline__ void cp_commit() {
    asm volatile("cp.async.commit_group;" ::: "memory");
}
__device__ __forceinline__ void cp_wait1() {
    asm volatile("cp.async.wait_group 1;" ::: "memory");
}
__device__ __forceinline__ uint32_t smem_u32(const void* p) {
    uint32_t a;
    asm("{ .reg .u64 t; cvta.to.shared.u64 t, %1; cvt.u32.u64 %0, t; }" : "=r"(a) : "l"(p));
    return a;
}
__device__ __forceinline__ float f2tf32(float x) {          // round-to-nearest tf32
    unsigned r;
    asm("cvt.rna.tf32.f32 %0, %1;" : "=r"(r) : "f"(x));
    return __uint_as_float(r);
}

// m16n8k8 tf32 mma (A pre-rounded rna; B HW-truncated from fp32 bits)
__device__ __forceinline__ void mma_tf32(float c[4], const float a[4], float b0, float b1) {
    asm volatile(
        "mma.sync.aligned.m16n8k8.row.col.f32.tf32.tf32.f32 "
        "{%0,%1,%2,%3}, {%4,%5,%6,%7}, {%8,%9}, {%0,%1,%2,%3};\n"
        : "+f"(c[0]), "+f"(c[1]), "+f"(c[2]), "+f"(c[3])
        : "r"(__float_as_uint(a[0])), "r"(__float_as_uint(a[1])),
          "r"(__float_as_uint(a[2])), "r"(__float_as_uint(a[3])),
          "r"(__float_as_uint(b0)), "r"(__float_as_uint(b1)));
}

// ---------------------------------------------------------------------------
// Deep path (passed R1, unchanged):  g = [hs|ht] @ W_L^T + b_L -> out[:,0:768]
// Also initializes out[:,768:1536] = b_L2 for the wide kernel's atomics.
// ---------------------------------------------------------------------------
#define DBM 64
#define DBN 64
#define DBK 16

__global__ __launch_bounds__(256)
void deep_kernel(const float* __restrict__ hs, const float* __restrict__ ht,
                 const float* __restrict__ WL, const float* __restrict__ bL,
                 const float* __restrict__ bL2, float* __restrict__ out)
{
    __shared__ float Xs[DBK][DBM + 8];
    __shared__ float Ws[DBK][DBN + 8];

    const int tid = threadIdx.x;
    const int tx  = tid & 15;
    const int ty  = tid >> 4;
    const int m0  = blockIdx.x * DBM;
    const int n0  = blockIdx.y * DBN;

    float acc[4][4];
#pragma unroll
    for (int i = 0; i < 4; ++i)
#pragma unroll
        for (int j = 0; j < 4; ++j) acc[i][j] = 0.f;

    for (int k0 = 0; k0 < 2 * D_SZ; k0 += DBK) {
        __syncthreads();
#pragma unroll
        for (int q = 0; q < 4; ++q) {
            int e  = tid + 256 * q;
            int kk = e & 15;
            int mm = e >> 4;
            int gk = k0 + kk;
            float xv = (gk < D_SZ) ? hs[(m0 + mm) * D_SZ + gk]
                                   : ht[(m0 + mm) * D_SZ + (gk - D_SZ)];
            Xs[kk][mm] = xv;
            Ws[kk][mm] = WL[(size_t)(n0 + mm) * (2 * D_SZ) + gk];
        }
        __syncthreads();
#pragma unroll
        for (int kk = 0; kk < DBK; ++kk) {
            float4 av = *(const float4*)&Xs[kk][ty * 4];
            float4 bv = *(const float4*)&Ws[kk][tx * 4];
            float a[4] = {av.x, av.y, av.z, av.w};
            float b[4] = {bv.x, bv.y, bv.z, bv.w};
#pragma unroll
            for (int i = 0; i < 4; ++i)
#pragma unroll
                for (int j = 0; j < 4; ++j) acc[i][j] += a[i] * b[j];
        }
    }

#pragma unroll
    for (int i = 0; i < 4; ++i) {
        int row = m0 + ty * 4 + i;
#pragma unroll
        for (int j = 0; j < 4; ++j) {
            int col = n0 + tx * 4 + j;
            out[(size_t)row * OUT_STR + col]         = acc[i][j] + bL[col];
            out[(size_t)row * OUT_STR + N_OUT + col] = bL2[col];
        }
    }
}

// ---------------------------------------------------------------------------
// Wide kernel: 512 threads = 16 warps (4m x 4n), warp tile 32x32.
// A fragments in registers: ht frags (per 128-chunk j-block) x hs scalars
// (per 8-chunk i-group). B: 3-buffer cp.async ring.
// Pipeline per chunk ch: wait_group 1 (ch landed) -> sync -> compute buf(ch%3)
// -> issue ch+2 into buf((ch+2)%3) -> commit. Issue target was last read at
// iteration ch-1; the barrier at top of ch bounds warp drift, so all readers
// provably finished before any writer issues.
// ---------------------------------------------------------------------------
__global__ __launch_bounds__(NTH, 1)
void wide_kernel(const float* __restrict__ hs, const float* __restrict__ ht,
                 const float* __restrict__ W2, float* __restrict__ out)
{
    extern __shared__ __align__(16) float smem[];
    float* Bsm = smem;                          // NBUF * BN * LDT
    float* Hts = smem + NBUF * B_WORDS;         // BM * LDT
    float* Hss = Hts + HTS_WORDS;               // IPG * BM

    const int tid  = threadIdx.x;
    const int lane = tid & 31;
    const int warp = tid >> 5;
    const int wm = (warp & 3) * 32;     // warp m offset
    const int wn = (warp >> 2) * 32;    // warp n offset
    const int r  = lane >> 2;           // 0..7
    const int c  = lane & 3;            // 0..3

    const int m0 = blockIdx.x * BM;
    const int n0 = blockIdx.y * BN;
    const int z  = blockIdx.z;
    const size_t kbase = (size_t)z * KSLICE;
    const int i0 = z * (KSLICE / D_SZ);

    // per-thread B staging coords (128 rows x 8 float4-segs = 1024 segs / 512 thr)
    const int srow0 = (tid * 2)     >> 3;
    const int skv0  = ((tid * 2)     & 7) * 4;
    const int srow1 = (tid * 2 + 1) >> 3;
    const int skv1  = ((tid * 2 + 1) & 7) * 4;
    const uint32_t sB = smem_u32(Bsm);

    float acc[2][4][4];
#pragma unroll
    for (int mi = 0; mi < 2; ++mi)
#pragma unroll
        for (int ni = 0; ni < 4; ++ni)
#pragma unroll
            for (int q = 0; q < 4; ++q) acc[mi][ni][q] = 0.f;

    float htr[4][2][4];   // ht fragments [kstep][mi][frag]

    // ---- prologue: issue chunks 0 and 1 (jc=0, i_loc=pc) ----
#pragma unroll
    for (int pc = 0; pc < 2; ++pc) {
        size_t gcol = kbase + (size_t)pc * D_SZ;
        uint32_t dbase = sB + (uint32_t)(pc * B_WORDS) * 4;
        cp_async16(dbase + (uint32_t)(srow0 * LDT + skv0) * 4,
                   W2 + (size_t)(n0 + srow0) * K_WIDE + gcol + skv0);
        cp_async16(dbase + (uint32_t)(srow1 * LDT + skv1) * 4,
                   W2 + (size_t)(n0 + srow1) * K_WIDE + gcol + skv1);
        cp_commit();
    }

    int buf = 0, pbuf = 2;   // compute buffer; prefetch buffer (= buf+2 mod 3)

#pragma unroll 1
    for (int ch = 0; ch < NCH; ++ch) {
        cp_wait1();          // chunk ch's group complete (ch+1 may pend)
        __syncthreads();     // B visible; all warps done with compute(ch-1)

        // ---- stage hs i-group (every 8 chunks) / ht j-block (every 128) ----
        if ((ch & 7) == 0) {
            const int jc = ch >> 7;
            const int ib = (ch >> 3) & 15;
            if ((ch & 127) == 0) {
#pragma unroll
                for (int s = 0; s < 2; ++s) {
                    int seg = tid * 2 + s;
                    int row = seg >> 3;
                    int kv  = (seg & 7) * 4;
                    float4 v = *(const float4*)(ht + (size_t)(m0 + row) * D_SZ + jc * BKC + kv);
                    *(float4*)&Hts[row * LDT + kv] = v;
                }
            }
#pragma unroll
            for (int s = 0; s < 2; ++s) {
                int e  = tid + NTH * s;
                int ii = e >> 7;
                int m  = e & 127;
                Hss[ii * BM + m] = __ldg(hs + (size_t)(m0 + m) * D_SZ + i0 + ib * IPG + ii);
            }
            __syncthreads();
            if ((ch & 127) == 0) {
#pragma unroll
                for (int ks = 0; ks < 4; ++ks)
#pragma unroll
                    for (int mi = 0; mi < 2; ++mi) {
                        int mrow = wm + mi * 16;
                        htr[ks][mi][0] = Hts[(mrow + r)     * LDT + ks * 8 + c];
                        htr[ks][mi][1] = Hts[(mrow + r + 8) * LDT + ks * 8 + c];
                        htr[ks][mi][2] = Hts[(mrow + r)     * LDT + ks * 8 + c + 4];
                        htr[ks][mi][3] = Hts[(mrow + r + 8) * LDT + ks * 8 + c + 4];
                    }
            }
        }

        // ---- compute chunk ch from Bsm[buf] ----
        {
            const float* Bb = Bsm + buf * B_WORDS;
            const int ii = ch & 7;
            float hsv[2][2];
            hsv[0][0] = Hss[ii * BM + wm + r];
            hsv[0][1] = Hss[ii * BM + wm + r + 8];
            hsv[1][0] = Hss[ii * BM + wm + 16 + r];
            hsv[1][1] = Hss[ii * BM + wm + 16 + r + 8];

#pragma unroll
            for (int ks = 0; ks < 4; ++ks) {
                float a[2][4];
#pragma unroll
                for (int mi = 0; mi < 2; ++mi) {
                    a[mi][0] = f2tf32(hsv[mi][0] * htr[ks][mi][0]);
                    a[mi][1] = f2tf32(hsv[mi][1] * htr[ks][mi][1]);
                    a[mi][2] = f2tf32(hsv[mi][0] * htr[ks][mi][2]);
                    a[mi][3] = f2tf32(hsv[mi][1] * htr[ks][mi][3]);
                }
#pragma unroll
                for (int ni = 0; ni < 4; ++ni) {
                    int nrow = wn + ni * 8 + r;
                    float b0 = Bb[nrow * LDT + ks * 8 + c];
                    float b1 = Bb[nrow * LDT + ks * 8 + c + 4];
                    mma_tf32(acc[0][ni], a[0], b0, b1);
                    mma_tf32(acc[1][ni], a[1], b0, b1);
                }
            }
        }

        // ---- issue chunk ch+2 into pbuf (safe: see header comment) ----
        if (ch + 2 < NCH) {
            int cn    = ch + 2;
            int jcn   = cn >> 7;
            int ilocn = ((cn >> 3) & 15) * IPG + (cn & 7);
            size_t gcol = kbase + (size_t)ilocn * D_SZ + jcn * BKC;
            uint32_t dbase = sB + (uint32_t)(pbuf * B_WORDS) * 4;
            cp_async16(dbase + (uint32_t)(srow0 * LDT + skv0) * 4,
                       W2 + (size_t)(n0 + srow0) * K_WIDE + gcol + skv0);
            cp_async16(dbase + (uint32_t)(srow1 * LDT + skv1) * 4,
                       W2 + (size_t)(n0 + srow1) * K_WIDE + gcol + skv1);
        }
        cp_commit();   // exactly one group per iteration (possibly empty)

        buf  = (buf  == NBUF - 1) ? 0 : buf + 1;
        pbuf = (pbuf == NBUF - 1) ? 0 : pbuf + 1;
    }

    // ---- epilogue: atomic accumulate onto bias-initialized out[:,768:1536] ----
#pragma unroll
    for (int mi = 0; mi < 2; ++mi) {
#pragma unroll
        for (int ni = 0; ni < 4; ++ni) {
            int row = m0 + wm + mi * 16 + r;
            int col = N_OUT + n0 + wn + ni * 8 + 2 * c;
            float* p0 = &out[(size_t)row * OUT_STR + col];
            atomicAdd(p0,     acc[mi][ni][0]);
            atomicAdd(p0 + 1, acc[mi][ni][1]);
            float* p1 = &out[(size_t)(row + 8) * OUT_STR + col];
            atomicAdd(p1,     acc[mi][ni][2]);
            atomicAdd(p1 + 1, acc[mi][ni][3]);
        }
    }
}

// ---------------------------------------------------------------------------
extern "C" void kernel_launch(void* const* d_in, const int* in_sizes, int n_in,
                              void* d_out, int out_size)
{
    const float* hs  = (const float*)d_in[0];
    const float* ht  = (const float*)d_in[1];
    const float* WL  = (const float*)d_in[2];
    const float* bL  = (const float*)d_in[3];
    const float* W2  = (const float*)d_in[4];
    const float* bL2 = (const float*)d_in[5];
    float* out = (float*)d_out;

    // deep path + bias init of wide region (same-stream ordering -> graph edge)
    deep_kernel<<<dim3(BATCH / DBM, N_OUT / DBN), 256>>>(hs, ht, WL, bL, bL2, out);

    // dynamic smem (76 KB > 48 KB static limit); attribute set is not an alloc
    cudaFuncSetAttribute(wide_kernel, cudaFuncAttributeMaxDynamicSharedMemorySize, SMEM_BYTES);

    // wide path: M fastest -> 8 co-scheduled M-CTAs share W2 slices in L2
    wide_kernel<<<dim3(BATCH / BM, N_OUT / BN, KSPLIT), NTH, SMEM_BYTES>>>(hs, ht, W2, out);
}